// round 15
// baseline (speedup 1.0000x reference)
#include <cuda_runtime.h>
#include <cuda_bf16.h>
#include <cuda_fp16.h>
#include <cstdint>

// ---------------- problem dims ----------------
#define PP 2
#define JJ 32
#define KK 32
#define MM 128
#define LL 16
#define NN 128
#define BATCH 512
#define KN 4096
#define JM 4096
#define BKC 64                 // GEMM K-chunk (fp16 elements)
#define NCHUNK (KN / BKC)      // 64
#define STAGE 24576            // bytes per pipeline stage (A 8KB + W 16KB)
#define NSTG 4
#define PREP_GRID 128
#define GEMM_CTAS 256

// ---------------- device scratch (no cudaMalloc allowed) ----------------
__device__ float g_pmax[PREP_GRID];
__device__ float g_pmin[PREP_GRID];
__device__ float g_scale;
__device__ unsigned g_cnt  = 0;
__device__ unsigned g_cnt2 = 0;
__device__ unsigned g_epoch = 0;            // incremented once per launch (by last gemm CTA)
__device__ unsigned g_gcnt  = 0;            // gemm completion counter
__device__ unsigned g_qdone = 0;            // q ready flag (== epoch)
__device__ unsigned g_wflag[JJ * KK];       // W tile ready flags (== epoch)
__device__ __half g_q[(size_t)BATCH * KN];  // quantized activations (exact ints, fp16)
__device__ __half g_W[(size_t)JM * KN];     // fp16 weight matrix

// ---------------- PTX helpers (sm_100-safe only) ----------------
__device__ __forceinline__ uint32_t smem_u32(const void* p) {
    uint32_t a;
    asm("{ .reg .u64 t; cvta.to.shared.u64 t, %1; cvt.u32.u64 %0, t; }" : "=r"(a) : "l"(p));
    return a;
}

__device__ __forceinline__ unsigned ld_acq(const unsigned* p) {
    unsigned v;
    asm volatile("ld.acquire.gpu.global.u32 %0, [%1];" : "=r"(v) : "l"(p) : "memory");
    return v;
}
__device__ __forceinline__ void st_rel(unsigned* p, unsigned v) {
    asm volatile("st.release.gpu.global.u32 [%0], %1;" :: "l"(p), "r"(v) : "memory");
}

__device__ __forceinline__ void cp16(uint32_t dst, const void* src) {
    asm volatile("cp.async.cg.shared.global [%0], [%1], 16;\n" :: "r"(dst), "l"(src));
}
#define CP_COMMIT() asm volatile("cp.async.commit_group;\n" ::: "memory")
#define CP_WAIT(n)  asm volatile("cp.async.wait_group %0;\n" :: "n"(n) : "memory")

__device__ __forceinline__ void ldsm4(uint32_t* r, uint32_t addr) {
    asm volatile("ldmatrix.sync.aligned.m8n8.x4.shared.b16 {%0,%1,%2,%3}, [%4];"
        : "=r"(r[0]), "=r"(r[1]), "=r"(r[2]), "=r"(r[3]) : "r"(addr));
}
__device__ __forceinline__ void ldsm4t(uint32_t* r, uint32_t addr) {
    asm volatile("ldmatrix.sync.aligned.m8n8.x4.trans.shared.b16 {%0,%1,%2,%3}, [%4];"
        : "=r"(r[0]), "=r"(r[1]), "=r"(r[2]), "=r"(r[3]) : "r"(addr));
}

// bf16 MMA (used in buildw where operands are exact small integers)
__device__ __forceinline__ void mma16816_bf(float* c, const uint32_t* a, const uint32_t* b) {
    asm volatile(
        "mma.sync.aligned.m16n8k16.row.col.f32.bf16.bf16.f32 "
        "{%0,%1,%2,%3}, {%4,%5,%6,%7}, {%8,%9}, {%0,%1,%2,%3};"
        : "+f"(c[0]), "+f"(c[1]), "+f"(c[2]), "+f"(c[3])
        : "r"(a[0]), "r"(a[1]), "r"(a[2]), "r"(a[3]), "r"(b[0]), "r"(b[1]));
}
// fp16 MMA with fp32 accum (main GEMM)
__device__ __forceinline__ void mma16816_f16(float* c, const uint32_t* a, const uint32_t* b) {
    asm volatile(
        "mma.sync.aligned.m16n8k16.row.col.f32.f16.f16.f32 "
        "{%0,%1,%2,%3}, {%4,%5,%6,%7}, {%8,%9}, {%0,%1,%2,%3};"
        : "+f"(c[0]), "+f"(c[1]), "+f"(c[2]), "+f"(c[3])
        : "r"(a[0]), "r"(a[1]), "r"(a[2]), "r"(a[3]), "r"(b[0]), "r"(b[1]));
}

// ---------------- smem layout for the fused prep+buildw kernel ----------------
#define YPITCH 24     // bf16 units per sY row (48 B)
#define ZPITCH 136    // bf16 units per sZ row (272 B)
#define OPITCH 136    // fp16 units per sO row (272 B)
#define SY_OFF  0          // bf16 [2][128*24]  = 12288 B
#define SZ_OFF  12288      // bf16 [2][16*136]  = 8704 B
#define SB_OFF  20992      // float[128]        = 512 B
#define SZR_OFF 21504      // float[128]        = 512 B
#define SO_OFF  22016      // half [128][136]   = 34816 B
#define BW_SMEM 56832

// ---------------- prep path: fused minmax + quant (CTAs 0..127, all wave-1 resident) ----------------
__device__ __forceinline__ void prep_body(const float* __restrict__ x, char* sm, unsigned ep) {
    float* smx = (float*)sm;           // 1024 B
    float* smn = (float*)(sm + 1024);  // 1024 B
    const float4* x4 = (const float4*)x;
    const int tid = threadIdx.x;
    const int base = blockIdx.x * 4096 + tid;

    float mx = -3.4e38f, mn = 3.4e38f;
#pragma unroll
    for (int i = 0; i < 16; i++) {
        float4 v = x4[base + i * 256];
        mx = fmaxf(mx, fmaxf(fmaxf(v.x, v.y), fmaxf(v.z, v.w)));
        mn = fminf(mn, fminf(fminf(v.x, v.y), fminf(v.z, v.w)));
    }
    smx[tid] = mx; smn[tid] = mn;
    __syncthreads();
    for (int s = 128; s > 0; s >>= 1) {
        if (tid < s) { smx[tid] = fmaxf(smx[tid], smx[tid + s]); smn[tid] = fminf(smn[tid], smn[tid + s]); }
        __syncthreads();
    }
    if (tid == 0) {
        g_pmax[blockIdx.x] = smx[0];
        g_pmin[blockIdx.x] = smn[0];
        __threadfence();
        atomicAdd(&g_cnt, 1u);
        while (atomicAdd(&g_cnt, 0u) < PREP_GRID) __nanosleep(64);
    }
    __syncthreads();

    // every prep CTA computes the identical scale from the 128 partials
    if (tid < PREP_GRID) { smx[tid] = g_pmax[tid]; smn[tid] = g_pmin[tid]; }
    __syncthreads();
    for (int s = 64; s > 0; s >>= 1) {
        if (tid < s) { smx[tid] = fmaxf(smx[tid], smx[tid + s]); smn[tid] = fminf(smn[tid], smn[tid + s]); }
        __syncthreads();
    }
    const float scl = fmaxf(__fdiv_rn(smx[0] - smn[0], 254.0f), 1e-8f);   // (max-min)/(2*qmax)
    if (blockIdx.x == 0 && tid == 0) g_scale = scl;

    // phase 2: quantize this CTA's chunk (x is L2-hot from phase 1)
#pragma unroll
    for (int i = 0; i < 16; i++) {
        const int e = base + i * 256;
        float4 v = x4[e];
        float q0 = fminf(fmaxf(rintf(__fdiv_rn(v.x, scl)), -127.f), 127.f);
        float q1 = fminf(fmaxf(rintf(__fdiv_rn(v.y, scl)), -127.f), 127.f);
        float q2 = fminf(fmaxf(rintf(__fdiv_rn(v.z, scl)), -127.f), 127.f);
        float q3 = fminf(fmaxf(rintf(__fdiv_rn(v.w, scl)), -127.f), 127.f);
        union { __half h[4]; uint2 u; } pk;
        pk.h[0] = __float2half_rn(q0);
        pk.h[1] = __float2half_rn(q1);
        pk.h[2] = __float2half_rn(q2);
        pk.h[3] = __float2half_rn(q3);
        ((uint2*)g_q)[e] = pk.u;
    }
    __syncthreads();
    if (tid == 0) {
        __threadfence();
        unsigned o = atomicAdd(&g_cnt2, 1u);
        if (o == PREP_GRID - 1) {
            g_cnt = 0; g_cnt2 = 0;          // reset for next replay
            st_rel(&g_qdone, ep);           // publish: q fully ready
        }
    }
}

// ---------------- buildw path: W tile per (j,k) with tensor cores ----------------
__device__ __forceinline__ void buildw_body(int bid, char* sm, unsigned ep,
                                            const float* __restrict__ Ysign,
                                            const float* __restrict__ Zsign,
                                            const float* __restrict__ Yscale,
                                            const float* __restrict__ Zscale,
                                            const float* __restrict__ Aq) {
    __nv_bfloat16* sY0 = (__nv_bfloat16*)(sm + SY_OFF);
    __nv_bfloat16* sY1 = (__nv_bfloat16*)(sm + SY_OFF + MM * YPITCH * 2);
    __nv_bfloat16* sZ0 = (__nv_bfloat16*)(sm + SZ_OFF);
    __nv_bfloat16* sZ1 = (__nv_bfloat16*)(sm + SZ_OFF + LL * ZPITCH * 2);
    float* sB  = (float*)(sm + SB_OFF);
    float* sZr = (float*)(sm + SZR_OFF);
    uint32_t* sO = (uint32_t*)(sm + SO_OFF);   // addressed in uint32 units

    // k-major tile order: early k-blocks finish first so the GEMM can start
    const int j = bid & 31;
    const int k = bid >> 5;
    const int tid = threadIdx.x;
    const int lane = tid & 31;
    const int wid = tid >> 5;

    float ysc[2], zsc[2], a0c[2], a1c[2], a2c[2];
    float a3s = 0.f;
#pragma unroll
    for (int p = 0; p < 2; p++) {
        int idx = (p * JJ + j) * KK + k;
        ysc[p] = Yscale[idx]; zsc[p] = Zscale[idx];
        a0c[p] = Aq[idx * 4 + 0]; a1c[p] = Aq[idx * 4 + 1];
        a2c[p] = Aq[idx * 4 + 2]; a3s += Aq[idx * 4 + 3];
        size_t base = (size_t)idx * (MM * LL);   // 2048 floats (== LL*NN)
        const float4* ys4 = (const float4*)(Ysign + base);
        const float4* zs4 = (const float4*)(Zsign + base);
        __nv_bfloat16* sYp = p ? sY1 : sY0;
        __nv_bfloat16* sZp = p ? sZ1 : sZ0;
#pragma unroll
        for (int i = 0; i < 2; i++) {
            int e4 = tid + i * 256;            // 0..511
            int e = e4 * 4;
            // Y: (m,l) with l fastest, 16 per row
            float4 v = ys4[e4];
            int m = e >> 4, l = e & 15;
            __nv_bfloat162* dy = (__nv_bfloat162*)(&sYp[m * YPITCH + l]);
            dy[0] = __nv_bfloat162{__float2bfloat16(v.x), __float2bfloat16(v.y)};
            dy[1] = __nv_bfloat162{__float2bfloat16(v.z), __float2bfloat16(v.w)};
            // Z: (l,n) with n fastest, 128 per row
            float4 w4 = zs4[e4];
            int zl = e >> 7, n = e & 127;
            __nv_bfloat162* dz = (__nv_bfloat162*)(&sZp[zl * ZPITCH + n]);
            dz[0] = __nv_bfloat162{__float2bfloat16(w4.x), __float2bfloat16(w4.y)};
            dz[1] = __nv_bfloat162{__float2bfloat16(w4.z), __float2bfloat16(w4.w)};
        }
    }
    __syncthreads();

    // row/col sign sums -> coefficient vectors
    if (tid < 128) {
        int m = tid; float s0 = 0.f, s1 = 0.f;
#pragma unroll
        for (int l = 0; l < 16; l++) {
            s0 += __bfloat162float(sY0[m * YPITCH + l]);
            s1 += __bfloat162float(sY1[m * YPITCH + l]);
        }
        sB[m] = a1c[0] * ysc[0] * s0 + a1c[1] * ysc[1] * s1;
    } else {
        int n = tid - 128; float s0 = 0.f, s1 = 0.f;
#pragma unroll
        for (int l = 0; l < 16; l++) {
            s0 += __bfloat162float(sZ0[l * ZPITCH + n]);
            s1 += __bfloat162float(sZ1[l * ZPITCH + n]);
        }
        sZr[n] = a2c[0] * zsc[0] * s0 + a2c[1] * zsc[1] * s1;
    }
    __syncthreads();

    const float c00 = a0c[0] * ysc[0] * zsc[0];
    const float c01 = a0c[1] * ysc[1] * zsc[1];
    const int mb = wid * 16;   // warp's m strip

    // A fragments (16x16, row-major m x l), one per p, loaded once
    uint32_t aoff = (uint32_t)((mb + (lane & 15)) * (YPITCH * 2)) + (uint32_t)((lane >> 4) * 16);
    uint32_t af0[4], af1[4];
    ldsm4(af0, smem_u32(sY0) + aoff);
    ldsm4(af1, smem_u32(sY1) + aoff);

    // B trans-ldsm lane addressing: source rows = l (k dim), cols = n
    uint32_t zoff = (uint32_t)((lane & 15) * (ZPITCH * 2)) + (uint32_t)(((lane >> 4) * 8) * 2);
    const uint32_t zb0 = smem_u32(sZ0) + zoff;
    const uint32_t zb1 = smem_u32(sZ1) + zoff;

    const int r0 = mb + (lane >> 2);
    const int r1 = r0 + 8;
    const float sb0 = sB[r0];
    const float sb1 = sB[r1];
    const int so0 = r0 * (OPITCH / 2);   // uint32 row base
    const int so1 = r1 * (OPITCH / 2);

#pragma unroll
    for (int nc = 0; nc < 4; nc++) {
        const int n0 = nc * 32;
        uint32_t b0a[4], b0b[4], b1a[4], b1b[4];
        ldsm4t(b0a, zb0 + (uint32_t)(n0 * 2));          // p0, n-tiles 0,1
        ldsm4t(b0b, zb0 + (uint32_t)((n0 + 16) * 2));   // p0, n-tiles 2,3
        ldsm4t(b1a, zb1 + (uint32_t)(n0 * 2));
        ldsm4t(b1b, zb1 + (uint32_t)((n0 + 16) * 2));

        float acc0[4][4], acc1[4][4];
#pragma unroll
        for (int t = 0; t < 4; t++)
#pragma unroll
            for (int v = 0; v < 4; v++) { acc0[t][v] = 0.f; acc1[t][v] = 0.f; }

        mma16816_bf(acc0[0], af0, &b0a[0]); mma16816_bf(acc0[1], af0, &b0a[2]);
        mma16816_bf(acc0[2], af0, &b0b[0]); mma16816_bf(acc0[3], af0, &b0b[2]);
        mma16816_bf(acc1[0], af1, &b1a[0]); mma16816_bf(acc1[1], af1, &b1a[2]);
        mma16816_bf(acc1[2], af1, &b1b[0]); mma16816_bf(acc1[3], af1, &b1b[2]);

#pragma unroll
        for (int nt = 0; nt < 4; nt++) {
            const int col = n0 + nt * 8 + (lane & 3) * 2;
            const float2 zr = *(const float2*)(&sZr[col]);
            const float add0 = zr.x + a3s;
            const float add1 = zr.y + a3s;
            float w00 = c00 * acc0[nt][0] + c01 * acc1[nt][0] + sb0 + add0;
            float w01 = c00 * acc0[nt][1] + c01 * acc1[nt][1] + sb0 + add1;
            float w10 = c00 * acc0[nt][2] + c01 * acc1[nt][2] + sb1 + add0;
            float w11 = c00 * acc0[nt][3] + c01 * acc1[nt][3] + sb1 + add1;

            union { __half h[2]; uint32_t u; } pk;
            pk.h[0] = __float2half_rn(w00); pk.h[1] = __float2half_rn(w01);
            sO[so0 + (col >> 1)] = pk.u;
            pk.h[0] = __float2half_rn(w10); pk.h[1] = __float2half_rn(w11);
            sO[so1 + (col >> 1)] = pk.u;
        }
    }
    __syncthreads();

    // coalesced store: 128 rows x 256 B, full 128B lines
    const char* sob = sm + SO_OFF;
    char* gw = (char*)(g_W + (size_t)(j * 128) * KN + k * 128);
#pragma unroll
    for (int it = 0; it < 8; it++) {
        int c = tid + it * 256;         // 0..2047
        int row = c >> 4;
        int seg = c & 15;
        uint4 v = *(const uint4*)(sob + row * (OPITCH * 2) + seg * 16);
        *(uint4*)(gw + (size_t)row * (KN * 2) + seg * 16) = v;
    }
    __syncthreads();
    if (tid == 0) {
        __threadfence();
        st_rel(&g_wflag[j * 32 + k], ep);   // publish: W tile (j,k) ready
    }
}

// ---------------- fused kernel: prep (CTAs 0..127) + buildw (CTAs 128..1151) ----------------
__global__ void __launch_bounds__(256) k_pb(const float* __restrict__ x,
                                            const float* __restrict__ Ysign,
                                            const float* __restrict__ Zsign,
                                            const float* __restrict__ Yscale,
                                            const float* __restrict__ Zscale,
                                            const float* __restrict__ Aq) {
    // allow the dependent GEMM grid to launch as soon as all pb blocks started
    cudaTriggerProgrammaticLaunchCompletion();
    extern __shared__ char sm[];
    const unsigned ep = *(volatile unsigned*)&g_epoch + 1;
    if (blockIdx.x < PREP_GRID) {
        prep_body(x, sm, ep);
    } else {
        buildw_body(blockIdx.x - PREP_GRID, sm, ep, Ysign, Zsign, Yscale, Zscale, Aq);
    }
}

// ---------------- kernel: warp-MMA GEMM out = act*(q @ W^T) + bias ----------------
// R13 configuration (the measured mma.sync fp32-accum floor): CTA tile 64x128,
// 128 threads = 4 warps (2m x 2n), warp tile 32x64, K-chunk 64, 4-stage pipeline,
// 2 CTAs/SM. Launched with PDL: readiness gated by epoch flags (g_qdone, g_wflag).
__global__ void __launch_bounds__(128, 2) k_gemm(const float* __restrict__ bias,
                                                 float* __restrict__ out) {
    extern __shared__ char smem[];
    const uint32_t sbase = smem_u32(smem);

    const int tid = threadIdx.x;
    const int lane = tid & 31;
    const int wid = tid >> 5;
    const int jt = blockIdx.x;        // jm tile, 0..31
    const int bt = blockIdx.y;        // b tile,  0..7 (64 rows each)
    const int warp_m = wid & 1;       // 0..1 -> m base warp_m*32
    const int warp_n = wid >> 1;      // 0..1 -> n base warp_n*64

    const unsigned ep = *(volatile unsigned*)&g_epoch + 1;
    const unsigned* wfl = &g_wflag[jt * 32];

    // ---- cp.async source/dest offsets ----
    uint32_t swoffA[4]; const char* srcq[4];
    uint32_t swoffW[8]; const char* srcw[8];
    {
        const char* gq = (const char*)(g_q + (size_t)(bt * 64) * KN);
        const char* gw = (const char*)(g_W + (size_t)(jt * 128) * KN);
#pragma unroll
        for (int i = 0; i < 4; i++) {
            int idx = tid + i * 128;            // 0..511
            int row = idx >> 3;                 // 0..63
            int seg = (idx & 7) * 16;
            swoffA[i] = (uint32_t)(row * 128) + ((uint32_t)seg ^ (uint32_t)((row & 7) << 4));
            srcq[i] = gq + (size_t)row * (KN * 2) + seg;
        }
#pragma unroll
        for (int i = 0; i < 8; i++) {
            int idx = tid + i * 128;            // 0..1023
            int row = idx >> 3;                 // 0..127
            int seg = (idx & 7) * 16;
            swoffW[i] = (uint32_t)(row * 128) + ((uint32_t)seg ^ (uint32_t)((row & 7) << 4));
            srcw[i] = gw + (size_t)row * (KN * 2) + seg;
        }
    }

    // ---- readiness gates for the preamble (q + W k-blocks 0,1) ----
    while (ld_acq(&g_qdone) != ep) { }
    while (ld_acq(&wfl[0]) != ep) { }
    while (ld_acq(&wfl[1]) != ep) { }

    // ---- prefetch chunks 0..2 ----
#pragma unroll
    for (int s = 0; s < NSTG - 1; s++) {
        uint32_t base = sbase + s * STAGE;
        size_t koff = (size_t)s * 128;          // 64 fp16 = 128 bytes
#pragma unroll
        for (int i = 0; i < 4; i++) cp16(base + swoffA[i], srcq[i] + koff);
#pragma unroll
        for (int i = 0; i < 8; i++) cp16(base + 8192 + swoffW[i], srcw[i] + koff);
        CP_COMMIT();
    }

    // ---- ldmatrix lane addressing ----
    const int a_row = warp_m * 32 + (lane & 15);           // + mt*16
    const uint32_t a_hi  = (uint32_t)((lane >> 4) * 16);
    const uint32_t a_swz = (uint32_t)((a_row & 7) << 4);   // invariant under +16
    const int b_g = lane >> 3;                              // 0..3
    const int b_row0 = warp_n * 64 + ((b_g >> 1) << 3) + (lane & 7);  // + i*16
    const uint32_t b_hi  = (uint32_t)((b_g & 1) * 16);
    const uint32_t b_swz = (uint32_t)((b_row0 & 7) << 4);  // invariant under +16

    float acc[2][8][4];
#pragma unroll
    for (int mt = 0; mt < 2; mt++)
#pragma unroll
        for (int nt = 0; nt < 8; nt++)
#pragma unroll
            for (int v = 0; v < 4; v++) acc[mt][nt][v] = 0.f;

    // register-double-buffered fragments
    uint32_t a_fr[2][2][4];   // [buf][mt][4]
    uint32_t b_fr[2][8][2];   // [buf][nt][2]

    for (int c = 0; c < NCHUNK; c++) {
        CP_WAIT(1);              // chunk c landed (only c+1's group may remain)
        __syncthreads();         // all threads see chunk c AND finished compute(c-1)

        // issue chunk c+3 into buffer (c+3)%4 == (c-1)%4, freed by the barrier above
        if (c + 3 < NCHUNK) {
            while (ld_acq(&wfl[(c + 3) >> 1]) != ep) { }   // W k-block ready?
            uint32_t base = sbase + ((c + 3) % NSTG) * STAGE;
            size_t koff = (size_t)(c + 3) * 128;
#pragma unroll
            for (int i = 0; i < 4; i++) cp16(base + swoffA[i], srcq[i] + koff);
#pragma unroll
            for (int i = 0; i < 8; i++) cp16(base + 8192 + swoffW[i], srcw[i] + koff);
        }
        CP_COMMIT();             // fixed group accounting (empty at tail)

        const uint32_t bb = sbase + (c % NSTG) * STAGE;

        // load ks=0 fragments into buf 0
#pragma unroll
        for (int mt = 0; mt < 2; mt++)
            ldsm4(a_fr[0][mt], bb + (uint32_t)((a_row + mt * 16) * 128) + (a_hi ^ a_swz));
#pragma unroll
        for (int i = 0; i < 4; i++) {
            uint32_t ro = (uint32_t)((b_row0 + i * 16) * 128) + (b_hi ^ b_swz);
            uint32_t r[4];
            ldsm4(r, bb + 8192 + ro);
            b_fr[0][2*i][0] = r[0]; b_fr[0][2*i][1] = r[1];
            b_fr[0][2*i+1][0] = r[2]; b_fr[0][2*i+1][1] = r[3];
        }

#pragma unroll
        for (int ks = 0; ks < 4; ks++) {
            const int cur = ks & 1;
            const int nxt = cur ^ 1;
            if (ks < 3) {
                const uint32_t kso = (uint32_t)((ks + 1) * 32);
#pragma unroll
                for (int mt = 0; mt < 2; mt++)
                    ldsm4(a_fr[nxt][mt], bb + (uint32_t)((a_row + mt * 16) * 128)
                                          + ((kso + a_hi) ^ a_swz));
#pragma unroll
                for (int i = 0; i < 4; i++) {
                    uint32_t ro = (uint32_t)((b_row0 + i * 16) * 128)
                                + ((kso + b_hi) ^ b_swz);
                    uint32_t r[4];
                    ldsm4(r, bb + 8192 + ro);
                    b_fr[nxt][2*i][0] = r[0]; b_fr[nxt][2*i][1] = r[1];
                    b_fr[nxt][2*i+1][0] = r[2]; b_fr[nxt][2*i+1][1] = r[3];
                }
            }
#pragma unroll
            for (int mt = 0; mt < 2; mt++)
#pragma unroll
                for (int nt = 0; nt < 8; nt++)
                    mma16816_f16(acc[mt][nt], a_fr[cur][mt], b_fr[cur][nt]);
        }
    }

    // ---- epilogue: out = acc*act + bias ----
    const float act = g_scale;
    const int orow0 = bt * 64 + warp_m * 32 + (lane >> 2);
    const int ocol0 = jt * 128 + warp_n * 64 + (lane & 3) * 2;
#pragma unroll
    for (int mt = 0; mt < 2; mt++) {
        const int r0 = orow0 + mt * 16;
#pragma unroll
        for (int nt = 0; nt < 8; nt++) {
            const int col = ocol0 + nt * 8;
            const float2 b2 = *(const float2*)(bias + col);
            float2 v0, v1;
            v0.x = acc[mt][nt][0] * act + b2.x;
            v0.y = acc[mt][nt][1] * act + b2.y;
            v1.x = acc[mt][nt][2] * act + b2.x;
            v1.y = acc[mt][nt][3] * act + b2.y;
            *(float2*)(out + (size_t)r0 * JM + col)       = v0;
            *(float2*)(out + (size_t)(r0 + 8) * JM + col) = v1;
        }
    }

    // ---- epoch advance: last gemm CTA of this launch bumps g_epoch ----
    __syncthreads();
    if (tid == 0) {
        unsigned o = atomicAdd(&g_gcnt, 1u);
        if (o == GEMM_CTAS - 1) {
            g_gcnt = 0;
            *(volatile unsigned*)&g_epoch = ep;
        }
    }
}

// ---------------- launcher ----------------
extern "C" void kernel_launch(void* const* d_in, const int* in_sizes, int n_in,
                              void* d_out, int out_size) {
    const float *x = nullptr, *Ys = nullptr, *Zs = nullptr;
    const float *Ysc = nullptr, *Zsc = nullptr, *A = nullptr, *bias = nullptr;
    for (int i = 0; i < n_in; i++) {
        const int s = in_sizes[i];
        const float* p = (const float*)d_in[i];
        if (s == BATCH * KN && !x) x = p;                                        // 2097152
        else if (s == PP * JJ * KK * MM * LL) { if (!Ys) Ys = p; else Zs = p; }  // 4194304 x2
        else if (s == PP * JJ * KK) { if (!Ysc) Ysc = p; else Zsc = p; }         // 2048 x2
        else if (s == PP * JJ * KK * 4) A = p;                                   // 8192
        else if (s == JM) bias = p;                                              // 4096
    }
    float* out = (float*)d_out;

    cudaFuncSetAttribute(k_pb, cudaFuncAttributeMaxDynamicSharedMemorySize, BW_SMEM);
    k_pb<<<PREP_GRID + JJ * KK, 256, BW_SMEM>>>(x, Ys, Zs, Ysc, Zsc, A);

    const int smem_bytes = NSTG * STAGE;   // 98304
    cudaFuncSetAttribute(k_gemm, cudaFuncAttributeMaxDynamicSharedMemorySize, smem_bytes);

    // PDL launch: gemm grid may begin while k_pb is still running; epoch flags
    // (g_qdone / g_wflag) gate every read of q and W, so overlap is safe, and if
    // PDL is unavailable the flags pass instantly (behavior == serial R13).
    cudaLaunchConfig_t cfg = {};
    cfg.gridDim = dim3(JM / 128, BATCH / 64, 1);
    cfg.blockDim = dim3(128, 1, 1);
    cfg.dynamicSmemBytes = smem_bytes;
    cfg.stream = 0;
    cudaLaunchAttribute attrs[1];
    attrs[0].id = cudaLaunchAttributeProgrammaticStreamSerialization;
    attrs[0].val.programmaticStreamSerializationAllowed = 1;
    cfg.attrs = attrs;
    cfg.numAttrs = 1;
    cudaLaunchKernelEx(&cfg, k_gemm, bias, out);
}

// round 16
// speedup vs baseline: 1.0287x; 1.0287x over previous
#include <cuda_runtime.h>
#include <cuda_bf16.h>
#include <cuda_fp16.h>
#include <cstdint>

// ---------------- problem dims ----------------
#define PP 2
#define JJ 32
#define KK 32
#define MM 128
#define LL 16
#define NN 128
#define BATCH 512
#define KN 4096
#define JM 4096
#define BKC 64                 // GEMM K-chunk (fp16 elements)
#define NCHUNK (KN / BKC)      // 64
#define STAGE 32768            // bytes per pipeline stage (A 16KB + W 16KB)
#define NSTG 4
#define PREP_GRID 128

// ---------------- device scratch (no cudaMalloc allowed) ----------------
__device__ float g_pmax[PREP_GRID];
__device__ float g_pmin[PREP_GRID];
__device__ float g_scale;
__device__ unsigned g_cnt  = 0;
__device__ unsigned g_cnt2 = 0;
__device__ __half g_q[(size_t)BATCH * KN];       // quantized activations (exact ints, fp16)
__device__ __half g_W[(size_t)JM * KN];          // fp16 weight matrix

// ---------------- PTX helpers (sm_100-safe only) ----------------
__device__ __forceinline__ uint32_t smem_u32(const void* p) {
    uint32_t a;
    asm("{ .reg .u64 t; cvta.to.shared.u64 t, %1; cvt.u32.u64 %0, t; }" : "=r"(a) : "l"(p));
    return a;
}

__device__ __forceinline__ void cp16(uint32_t dst, const void* src) {
    asm volatile("cp.async.cg.shared.global [%0], [%1], 16;\n" :: "r"(dst), "l"(src));
}
#define CP_COMMIT() asm volatile("cp.async.commit_group;\n" ::: "memory")
#define CP_WAIT(n)  asm volatile("cp.async.wait_group %0;\n" :: "n"(n) : "memory")

__device__ __forceinline__ void ldsm4(uint32_t* r, uint32_t addr) {
    asm volatile("ldmatrix.sync.aligned.m8n8.x4.shared.b16 {%0,%1,%2,%3}, [%4];"
        : "=r"(r[0]), "=r"(r[1]), "=r"(r[2]), "=r"(r[3]) : "r"(addr));
}
__device__ __forceinline__ void ldsm4t(uint32_t* r, uint32_t addr) {
    asm volatile("ldmatrix.sync.aligned.m8n8.x4.trans.shared.b16 {%0,%1,%2,%3}, [%4];"
        : "=r"(r[0]), "=r"(r[1]), "=r"(r[2]), "=r"(r[3]) : "r"(addr));
}

// bf16 MMA (used in buildw where operands are exact small integers)
__device__ __forceinline__ void mma16816_bf(float* c, const uint32_t* a, const uint32_t* b) {
    asm volatile(
        "mma.sync.aligned.m16n8k16.row.col.f32.bf16.bf16.f32 "
        "{%0,%1,%2,%3}, {%4,%5,%6,%7}, {%8,%9}, {%0,%1,%2,%3};"
        : "+f"(c[0]), "+f"(c[1]), "+f"(c[2]), "+f"(c[3])
        : "r"(a[0]), "r"(a[1]), "r"(a[2]), "r"(a[3]), "r"(b[0]), "r"(b[1]));
}
// fp16 MMA with fp32 accum (main GEMM)
__device__ __forceinline__ void mma16816_f16(float* c, const uint32_t* a, const uint32_t* b) {
    asm volatile(
        "mma.sync.aligned.m16n8k16.row.col.f32.f16.f16.f32 "
        "{%0,%1,%2,%3}, {%4,%5,%6,%7}, {%8,%9}, {%0,%1,%2,%3};"
        : "+f"(c[0]), "+f"(c[1]), "+f"(c[2]), "+f"(c[3])
        : "r"(a[0]), "r"(a[1]), "r"(a[2]), "r"(a[3]), "r"(b[0]), "r"(b[1]));
}

// ---------------- smem layout for the fused prep+buildw kernel ----------------
#define YPITCH 24     // bf16 units per sY row (48 B)
#define ZPITCH 136    // bf16 units per sZ row (272 B)
#define OPITCH 136    // fp16 units per sO row (272 B)
#define SY_OFF  0          // bf16 [2][128*24]  = 12288 B
#define SZ_OFF  12288      // bf16 [2][16*136]  = 8704 B
#define SB_OFF  20992      // float[128]        = 512 B
#define SZR_OFF 21504      // float[128]        = 512 B
#define SO_OFF  22016      // half [128][136]   = 34816 B
#define BW_SMEM 56832

// ---------------- prep path: fused minmax + quant (CTAs 0..127, all wave-1 resident) ----------------
__device__ __forceinline__ void prep_body(const float* __restrict__ x, char* sm) {
    float* smx = (float*)sm;           // 1024 B
    float* smn = (float*)(sm + 1024);  // 1024 B
    const float4* x4 = (const float4*)x;
    const int tid = threadIdx.x;
    const int base = blockIdx.x * 4096 + tid;

    float mx = -3.4e38f, mn = 3.4e38f;
#pragma unroll
    for (int i = 0; i < 16; i++) {
        float4 v = x4[base + i * 256];
        mx = fmaxf(mx, fmaxf(fmaxf(v.x, v.y), fmaxf(v.z, v.w)));
        mn = fminf(mn, fminf(fminf(v.x, v.y), fminf(v.z, v.w)));
    }
    smx[tid] = mx; smn[tid] = mn;
    __syncthreads();
    for (int s = 128; s > 0; s >>= 1) {
        if (tid < s) { smx[tid] = fmaxf(smx[tid], smx[tid + s]); smn[tid] = fminf(smn[tid], smn[tid + s]); }
        __syncthreads();
    }
    if (tid == 0) {
        g_pmax[blockIdx.x] = smx[0];
        g_pmin[blockIdx.x] = smn[0];
        __threadfence();
        atomicAdd(&g_cnt, 1u);
        while (atomicAdd(&g_cnt, 0u) < PREP_GRID) __nanosleep(64);
    }
    __syncthreads();

    // every prep CTA computes the identical scale from the 128 partials
    if (tid < PREP_GRID) { smx[tid] = g_pmax[tid]; smn[tid] = g_pmin[tid]; }
    __syncthreads();
    for (int s = 64; s > 0; s >>= 1) {
        if (tid < s) { smx[tid] = fmaxf(smx[tid], smx[tid + s]); smn[tid] = fminf(smn[tid], smn[tid + s]); }
        __syncthreads();
    }
    const float scl = fmaxf(__fdiv_rn(smx[0] - smn[0], 254.0f), 1e-8f);   // (max-min)/(2*qmax)
    if (blockIdx.x == 0 && tid == 0) g_scale = scl;

    // phase 2: quantize this CTA's chunk (x is L2-hot from phase 1)
#pragma unroll
    for (int i = 0; i < 16; i++) {
        const int e = base + i * 256;
        float4 v = x4[e];
        float q0 = fminf(fmaxf(rintf(__fdiv_rn(v.x, scl)), -127.f), 127.f);
        float q1 = fminf(fmaxf(rintf(__fdiv_rn(v.y, scl)), -127.f), 127.f);
        float q2 = fminf(fmaxf(rintf(__fdiv_rn(v.z, scl)), -127.f), 127.f);
        float q3 = fminf(fmaxf(rintf(__fdiv_rn(v.w, scl)), -127.f), 127.f);
        union { __half h[4]; uint2 u; } pk;
        pk.h[0] = __float2half_rn(q0);
        pk.h[1] = __float2half_rn(q1);
        pk.h[2] = __float2half_rn(q2);
        pk.h[3] = __float2half_rn(q3);
        ((uint2*)g_q)[e] = pk.u;
    }
    __syncthreads();
    if (tid == 0) {
        unsigned o = atomicAdd(&g_cnt2, 1u);
        if (o == PREP_GRID - 1) { g_cnt = 0; g_cnt2 = 0; }   // reset for next replay
    }
}

// ---------------- buildw path: W tile per (j,k) with tensor cores ----------------
__device__ __forceinline__ void buildw_body(int bid, char* sm,
                                            const float* __restrict__ Ysign,
                                            const float* __restrict__ Zsign,
                                            const float* __restrict__ Yscale,
                                            const float* __restrict__ Zscale,
                                            const float* __restrict__ Aq) {
    __nv_bfloat16* sY0 = (__nv_bfloat16*)(sm + SY_OFF);
    __nv_bfloat16* sY1 = (__nv_bfloat16*)(sm + SY_OFF + MM * YPITCH * 2);
    __nv_bfloat16* sZ0 = (__nv_bfloat16*)(sm + SZ_OFF);
    __nv_bfloat16* sZ1 = (__nv_bfloat16*)(sm + SZ_OFF + LL * ZPITCH * 2);
    float* sB  = (float*)(sm + SB_OFF);
    float* sZr = (float*)(sm + SZR_OFF);
    uint32_t* sO = (uint32_t*)(sm + SO_OFF);   // addressed in uint32 units

    const int j = bid >> 5;
    const int k = bid & 31;
    const int tid = threadIdx.x;
    const int lane = tid & 31;
    const int wid = tid >> 5;

    float ysc[2], zsc[2], a0c[2], a1c[2], a2c[2];
    float a3s = 0.f;
#pragma unroll
    for (int p = 0; p < 2; p++) {
        int idx = (p * JJ + j) * KK + k;
        ysc[p] = Yscale[idx]; zsc[p] = Zscale[idx];
        a0c[p] = Aq[idx * 4 + 0]; a1c[p] = Aq[idx * 4 + 1];
        a2c[p] = Aq[idx * 4 + 2]; a3s += Aq[idx * 4 + 3];
        size_t base = (size_t)idx * (MM * LL);   // 2048 floats (== LL*NN)
        const float4* ys4 = (const float4*)(Ysign + base);
        const float4* zs4 = (const float4*)(Zsign + base);
        __nv_bfloat16* sYp = p ? sY1 : sY0;
        __nv_bfloat16* sZp = p ? sZ1 : sZ0;
#pragma unroll
        for (int i = 0; i < 2; i++) {
            int e4 = tid + i * 256;            // 0..511
            int e = e4 * 4;
            // Y: (m,l) with l fastest, 16 per row
            float4 v = ys4[e4];
            int m = e >> 4, l = e & 15;
            __nv_bfloat162* dy = (__nv_bfloat162*)(&sYp[m * YPITCH + l]);
            dy[0] = __nv_bfloat162{__float2bfloat16(v.x), __float2bfloat16(v.y)};
            dy[1] = __nv_bfloat162{__float2bfloat16(v.z), __float2bfloat16(v.w)};
            // Z: (l,n) with n fastest, 128 per row
            float4 w4 = zs4[e4];
            int zl = e >> 7, n = e & 127;
            __nv_bfloat162* dz = (__nv_bfloat162*)(&sZp[zl * ZPITCH + n]);
            dz[0] = __nv_bfloat162{__float2bfloat16(w4.x), __float2bfloat16(w4.y)};
            dz[1] = __nv_bfloat162{__float2bfloat16(w4.z), __float2bfloat16(w4.w)};
        }
    }
    __syncthreads();

    // row/col sign sums -> coefficient vectors
    if (tid < 128) {
        int m = tid; float s0 = 0.f, s1 = 0.f;
#pragma unroll
        for (int l = 0; l < 16; l++) {
            s0 += __bfloat162float(sY0[m * YPITCH + l]);
            s1 += __bfloat162float(sY1[m * YPITCH + l]);
        }
        sB[m] = a1c[0] * ysc[0] * s0 + a1c[1] * ysc[1] * s1;
    } else {
        int n = tid - 128; float s0 = 0.f, s1 = 0.f;
#pragma unroll
        for (int l = 0; l < 16; l++) {
            s0 += __bfloat162float(sZ0[l * ZPITCH + n]);
            s1 += __bfloat162float(sZ1[l * ZPITCH + n]);
        }
        sZr[n] = a2c[0] * zsc[0] * s0 + a2c[1] * zsc[1] * s1;
    }
    __syncthreads();

    const float c00 = a0c[0] * ysc[0] * zsc[0];
    const float c01 = a0c[1] * ysc[1] * zsc[1];
    const int mb = wid * 16;   // warp's m strip

    // A fragments (16x16, row-major m x l), one per p, loaded once
    uint32_t aoff = (uint32_t)((mb + (lane & 15)) * (YPITCH * 2)) + (uint32_t)((lane >> 4) * 16);
    uint32_t af0[4], af1[4];
    ldsm4(af0, smem_u32(sY0) + aoff);
    ldsm4(af1, smem_u32(sY1) + aoff);

    // B trans-ldsm lane addressing: source rows = l (k dim), cols = n
    uint32_t zoff = (uint32_t)((lane & 15) * (ZPITCH * 2)) + (uint32_t)(((lane >> 4) * 8) * 2);
    const uint32_t zb0 = smem_u32(sZ0) + zoff;
    const uint32_t zb1 = smem_u32(sZ1) + zoff;

    const int r0 = mb + (lane >> 2);
    const int r1 = r0 + 8;
    const float sb0 = sB[r0];
    const float sb1 = sB[r1];
    const int so0 = r0 * (OPITCH / 2);   // uint32 row base
    const int so1 = r1 * (OPITCH / 2);

#pragma unroll
    for (int nc = 0; nc < 4; nc++) {
        const int n0 = nc * 32;
        uint32_t b0a[4], b0b[4], b1a[4], b1b[4];
        ldsm4t(b0a, zb0 + (uint32_t)(n0 * 2));          // p0, n-tiles 0,1
        ldsm4t(b0b, zb0 + (uint32_t)((n0 + 16) * 2));   // p0, n-tiles 2,3
        ldsm4t(b1a, zb1 + (uint32_t)(n0 * 2));
        ldsm4t(b1b, zb1 + (uint32_t)((n0 + 16) * 2));

        float acc0[4][4], acc1[4][4];
#pragma unroll
        for (int t = 0; t < 4; t++)
#pragma unroll
            for (int v = 0; v < 4; v++) { acc0[t][v] = 0.f; acc1[t][v] = 0.f; }

        mma16816_bf(acc0[0], af0, &b0a[0]); mma16816_bf(acc0[1], af0, &b0a[2]);
        mma16816_bf(acc0[2], af0, &b0b[0]); mma16816_bf(acc0[3], af0, &b0b[2]);
        mma16816_bf(acc1[0], af1, &b1a[0]); mma16816_bf(acc1[1], af1, &b1a[2]);
        mma16816_bf(acc1[2], af1, &b1b[0]); mma16816_bf(acc1[3], af1, &b1b[2]);

#pragma unroll
        for (int nt = 0; nt < 4; nt++) {
            const int col = n0 + nt * 8 + (lane & 3) * 2;
            const float2 zr = *(const float2*)(&sZr[col]);
            const float add0 = zr.x + a3s;
            const float add1 = zr.y + a3s;
            float w00 = c00 * acc0[nt][0] + c01 * acc1[nt][0] + sb0 + add0;
            float w01 = c00 * acc0[nt][1] + c01 * acc1[nt][1] + sb0 + add1;
            float w10 = c00 * acc0[nt][2] + c01 * acc1[nt][2] + sb1 + add0;
            float w11 = c00 * acc0[nt][3] + c01 * acc1[nt][3] + sb1 + add1;

            union { __half h[2]; uint32_t u; } pk;
            pk.h[0] = __float2half_rn(w00); pk.h[1] = __float2half_rn(w01);
            sO[so0 + (col >> 1)] = pk.u;
            pk.h[0] = __float2half_rn(w10); pk.h[1] = __float2half_rn(w11);
            sO[so1 + (col >> 1)] = pk.u;
        }
    }
    __syncthreads();

    // coalesced store: 128 rows x 256 B, full 128B lines
    const char* sob = sm + SO_OFF;
    char* gw = (char*)(g_W + (size_t)(j * 128) * KN + k * 128);
#pragma unroll
    for (int it = 0; it < 8; it++) {
        int c = tid + it * 256;         // 0..2047
        int row = c >> 4;
        int seg = c & 15;
        uint4 v = *(const uint4*)(sob + row * (OPITCH * 2) + seg * 16);
        *(uint4*)(gw + (size_t)row * (KN * 2) + seg * 16) = v;
    }
}

// ---------------- fused kernel: prep (CTAs 0..127) + buildw (CTAs 128..1151) ----------------
__global__ void __launch_bounds__(256) k_pb(const float* __restrict__ x,
                                            const float* __restrict__ Ysign,
                                            const float* __restrict__ Zsign,
                                            const float* __restrict__ Yscale,
                                            const float* __restrict__ Zscale,
                                            const float* __restrict__ Aq) {
    extern __shared__ char sm[];
    if (blockIdx.x < PREP_GRID) {
        prep_body(x, sm);
    } else {
        buildw_body(blockIdx.x - PREP_GRID, sm, Ysign, Zsign, Yscale, Zscale, Aq);
    }
}

// ---------------- kernel: warp-MMA GEMM out = act*(q @ W^T) + bias ----------------
// CTA tile 128(b) x 128(jm), 128 threads = 4 warps (2m x 2n), WARP TILE 64x64.
// Halved smem traffic per FLOP vs 32x64 warp tiles: per chunk 64KB ldsm reads
// + 32KB cp.async writes for 4.2 MFLOP -> smem ~770 cyc << MMA ~2048 cyc.
// K-chunk 64, 4-stage pipeline (32KB/stage = 128KB), grid 32x4 = 128 CTAs.
__global__ void __launch_bounds__(128, 1) k_gemm(const float* __restrict__ bias,
                                                 float* __restrict__ out) {
    extern __shared__ char smem[];
    const uint32_t sbase = smem_u32(smem);

    const int tid = threadIdx.x;
    const int lane = tid & 31;
    const int wid = tid >> 5;
    const int jt = blockIdx.x;        // jm tile, 0..31
    const int bt = blockIdx.y;        // b tile,  0..3 (128 rows each)
    const int warp_m = wid & 1;       // 0..1 -> m base warp_m*64
    const int warp_n = wid >> 1;      // 0..1 -> n base warp_n*64

    // ---- cp.async source/dest offsets: 8 x 16B per tile per thread ----
    uint32_t swoff[8];
    const char* srcq[8];
    const char* srcw[8];
    {
        const char* gq = (const char*)(g_q + (size_t)(bt * 128) * KN);
        const char* gw = (const char*)(g_W + (size_t)(jt * 128) * KN);
#pragma unroll
        for (int i = 0; i < 8; i++) {
            int idx = tid + i * 128;            // 0..1023
            int row = idx >> 3;                 // 0..127
            int seg = (idx & 7) * 16;
            swoff[i] = (uint32_t)(row * 128) + ((uint32_t)seg ^ (uint32_t)((row & 7) << 4));
            size_t gb = (size_t)row * (KN * 2) + seg;
            srcq[i] = gq + gb;
            srcw[i] = gw + gb;
        }
    }

    // ---- prefetch chunks 0..2 ----
#pragma unroll
    for (int s = 0; s < NSTG - 1; s++) {
        uint32_t base = sbase + s * STAGE;
        size_t koff = (size_t)s * 128;          // 64 fp16 = 128 bytes
#pragma unroll
        for (int i = 0; i < 8; i++) {
            cp16(base +         swoff[i], srcq[i] + koff);
            cp16(base + 16384 + swoff[i], srcw[i] + koff);
        }
        CP_COMMIT();
    }

    // ---- ldmatrix lane addressing ----
    const int a_row = warp_m * 64 + (lane & 15);           // + mt*16, mt 0..3
    const uint32_t a_hi  = (uint32_t)((lane >> 4) * 16);
    const uint32_t a_swz = (uint32_t)((a_row & 7) << 4);   // invariant under +16
    const int b_g = lane >> 3;                              // 0..3
    const int b_row0 = warp_n * 64 + ((b_g >> 1) << 3) + (lane & 7);  // + i*16, i 0..3
    const uint32_t b_hi  = (uint32_t)((b_g & 1) * 16);
    const uint32_t b_swz = (uint32_t)((b_row0 & 7) << 4);  // invariant under +16

    float acc[4][8][4];
#pragma unroll
    for (int mt = 0; mt < 4; mt++)
#pragma unroll
        for (int nt = 0; nt < 8; nt++)
#pragma unroll
            for (int v = 0; v < 4; v++) acc[mt][nt][v] = 0.f;

    for (int c = 0; c < NCHUNK; c++) {
        CP_WAIT(1);              // chunk c landed (only c+1's group may remain)
        __syncthreads();         // all threads see chunk c AND finished compute(c-1)

        // issue chunk c+3 into buffer (c+3)%4 == (c-1)%4, freed by the barrier above
        if (c + 3 < NCHUNK) {
            uint32_t base = sbase + ((c + 3) % NSTG) * STAGE;
            size_t koff = (size_t)(c + 3) * 128;
#pragma unroll
            for (int i = 0; i < 8; i++) {
                cp16(base +         swoff[i], srcq[i] + koff);
                cp16(base + 16384 + swoff[i], srcw[i] + koff);
            }
        }
        CP_COMMIT();             // fixed group accounting (empty at tail)

        const uint32_t bb = sbase + (c % NSTG) * STAGE;
#pragma unroll
        for (int ks = 0; ks < 4; ks++) {
            const uint32_t kso = (uint32_t)(ks * 32);
            uint32_t a[4][4];
#pragma unroll
            for (int mt = 0; mt < 4; mt++)
                ldsm4(a[mt], bb + (uint32_t)((a_row + mt * 16) * 128)
                              + ((kso + a_hi) ^ a_swz));
            uint32_t bw[8][2];
#pragma unroll
            for (int i = 0; i < 4; i++) {
                uint32_t ro = (uint32_t)((b_row0 + i * 16) * 128)
                            + ((kso + b_hi) ^ b_swz);
                uint32_t r[4];
                ldsm4(r, bb + 16384 + ro);
                bw[2*i][0] = r[0]; bw[2*i][1] = r[1]; bw[2*i+1][0] = r[2]; bw[2*i+1][1] = r[3];
            }
#pragma unroll
            for (int mt = 0; mt < 4; mt++)
#pragma unroll
                for (int nt = 0; nt < 8; nt++)
                    mma16816_f16(acc[mt][nt], a[mt], bw[nt]);
        }
    }

    // ---- epilogue: out = acc*act + bias ----
    const float act = g_scale;
    const int orow0 = bt * 128 + warp_m * 64 + (lane >> 2);
    const int ocol0 = jt * 128 + warp_n * 64 + (lane & 3) * 2;
#pragma unroll
    for (int mt = 0; mt < 4; mt++) {
        const int r0 = orow0 + mt * 16;
#pragma unroll
        for (int nt = 0; nt < 8; nt++) {
            const int col = ocol0 + nt * 8;
            const float2 b2 = *(const float2*)(bias + col);
            float2 v0, v1;
            v0.x = acc[mt][nt][0] * act + b2.x;
            v0.y = acc[mt][nt][1] * act + b2.y;
            v1.x = acc[mt][nt][2] * act + b2.x;
            v1.y = acc[mt][nt][3] * act + b2.y;
            *(float2*)(out + (size_t)r0 * JM + col)       = v0;
            *(float2*)(out + (size_t)(r0 + 8) * JM + col) = v1;
        }
    }
}

// ---------------- launcher ----------------
extern "C" void kernel_launch(void* const* d_in, const int* in_sizes, int n_in,
                              void* d_out, int out_size) {
    const float *x = nullptr, *Ys = nullptr, *Zs = nullptr;
    const float *Ysc = nullptr, *Zsc = nullptr, *A = nullptr, *bias = nullptr;
    for (int i = 0; i < n_in; i++) {
        const int s = in_sizes[i];
        const float* p = (const float*)d_in[i];
        if (s == BATCH * KN && !x) x = p;                                        // 2097152
        else if (s == PP * JJ * KK * MM * LL) { if (!Ys) Ys = p; else Zs = p; }  // 4194304 x2
        else if (s == PP * JJ * KK) { if (!Ysc) Ysc = p; else Zsc = p; }         // 2048 x2
        else if (s == PP * JJ * KK * 4) A = p;                                   // 8192
        else if (s == JM) bias = p;                                              // 4096
    }
    float* out = (float*)d_out;

    cudaFuncSetAttribute(k_pb, cudaFuncAttributeMaxDynamicSharedMemorySize, BW_SMEM);
    k_pb<<<PREP_GRID + JJ * KK, 256, BW_SMEM>>>(x, Ys, Zs, Ysc, Zsc, A);

    const int smem_bytes = NSTG * STAGE;   // 131072
    cudaFuncSetAttribute(k_gemm, cudaFuncAttributeMaxDynamicSharedMemorySize, smem_bytes);
    dim3 grid(JM / 128, BATCH / 128);
    k_gemm<<<grid, 128, smem_bytes>>>(bias, out);
}

// round 17
// speedup vs baseline: 1.0895x; 1.0591x over previous
#include <cuda_runtime.h>
#include <cuda_bf16.h>
#include <cuda_fp16.h>
#include <cstdint>

// ---------------- problem dims ----------------
#define PP 2
#define JJ 32
#define KK 32
#define MM 128
#define LL 16
#define NN 128
#define BATCH 512
#define KN 4096
#define JM 4096
#define BKC 64                 // GEMM K-chunk (fp16 elements)
#define NCHUNK (KN / BKC)      // 64
#define STAGE 24576            // bytes per pipeline stage (A 8KB + W 16KB)
#define NSTG 4
#define PREP_GRID 128

// ---------------- device scratch (no cudaMalloc allowed) ----------------
__device__ float g_pmax[PREP_GRID];
__device__ float g_pmin[PREP_GRID];
__device__ float g_scale;
__device__ unsigned g_cnt  = 0;
__device__ unsigned g_cnt2 = 0;
__device__ __half g_q[(size_t)BATCH * KN];       // quantized activations (exact ints, fp16)
__device__ __half g_W[(size_t)JM * KN];          // fp16 weight matrix

// ---------------- PTX helpers (sm_100-safe only) ----------------
__device__ __forceinline__ uint32_t smem_u32(const void* p) {
    uint32_t a;
    asm("{ .reg .u64 t; cvta.to.shared.u64 t, %1; cvt.u32.u64 %0, t; }" : "=r"(a) : "l"(p));
    return a;
}

__device__ __forceinline__ void cp16(uint32_t dst, const void* src) {
    asm volatile("cp.async.cg.shared.global [%0], [%1], 16;\n" :: "r"(dst), "l"(src));
}
#define CP_COMMIT() asm volatile("cp.async.commit_group;\n" ::: "memory")
#define CP_WAIT(n)  asm volatile("cp.async.wait_group %0;\n" :: "n"(n) : "memory")

__device__ __forceinline__ void ldsm4(uint32_t* r, uint32_t addr) {
    asm volatile("ldmatrix.sync.aligned.m8n8.x4.shared.b16 {%0,%1,%2,%3}, [%4];"
        : "=r"(r[0]), "=r"(r[1]), "=r"(r[2]), "=r"(r[3]) : "r"(addr));
}
__device__ __forceinline__ void ldsm4t(uint32_t* r, uint32_t addr) {
    asm volatile("ldmatrix.sync.aligned.m8n8.x4.trans.shared.b16 {%0,%1,%2,%3}, [%4];"
        : "=r"(r[0]), "=r"(r[1]), "=r"(r[2]), "=r"(r[3]) : "r"(addr));
}

// bf16 MMA (used in buildw where operands are exact small integers)
__device__ __forceinline__ void mma16816_bf(float* c, const uint32_t* a, const uint32_t* b) {
    asm volatile(
        "mma.sync.aligned.m16n8k16.row.col.f32.bf16.bf16.f32 "
        "{%0,%1,%2,%3}, {%4,%5,%6,%7}, {%8,%9}, {%0,%1,%2,%3};"
        : "+f"(c[0]), "+f"(c[1]), "+f"(c[2]), "+f"(c[3])
        : "r"(a[0]), "r"(a[1]), "r"(a[2]), "r"(a[3]), "r"(b[0]), "r"(b[1]));
}
// fp16 MMA with fp32 accum (main GEMM)
__device__ __forceinline__ void mma16816_f16(float* c, const uint32_t* a, const uint32_t* b) {
    asm volatile(
        "mma.sync.aligned.m16n8k16.row.col.f32.f16.f16.f32 "
        "{%0,%1,%2,%3}, {%4,%5,%6,%7}, {%8,%9}, {%0,%1,%2,%3};"
        : "+f"(c[0]), "+f"(c[1]), "+f"(c[2]), "+f"(c[3])
        : "r"(a[0]), "r"(a[1]), "r"(a[2]), "r"(a[3]), "r"(b[0]), "r"(b[1]));
}

// ---------------- smem layout for the fused prep+buildw kernel ----------------
// sY is DEAD after the A-fragment ldsm, so sO overlays it (saves 12.3 KB):
//   sZ  @0      : bf16 [2][16*136] = 8704 B
//   sB  @8704   : float[128]       = 512 B
//   sZr @9216   : float[128]       = 512 B
//   sY  @9728   : bf16 [2][128*24] = 12288 B   (dead after af ldsm)
//   sO  @9728   : half [128][136]  = 34816 B   (overlays sY; barrier in between)
#define YPITCH 24     // bf16 units per sY row (48 B)
#define ZPITCH 136    // bf16 units per sZ row (272 B)
#define OPITCH 136    // fp16 units per sO row (272 B)
#define SZ_OFF  0
#define SB_OFF  8704
#define SZR_OFF 9216
#define SY_OFF  9728
#define SO_OFF  9728
#define BW_SMEM 44544

// ---------------- prep path: fused minmax + quant (CTAs 0..127, all wave-1 resident) ----------------
__device__ __forceinline__ void prep_body(const float* __restrict__ x, char* sm) {
    float* smx = (float*)sm;           // 1024 B
    float* smn = (float*)(sm + 1024);  // 1024 B
    const float4* x4 = (const float4*)x;
    const int tid = threadIdx.x;
    const int base = blockIdx.x * 4096 + tid;

    float mx = -3.4e38f, mn = 3.4e38f;
#pragma unroll
    for (int i = 0; i < 16; i++) {
        float4 v = x4[base + i * 256];
        mx = fmaxf(mx, fmaxf(fmaxf(v.x, v.y), fmaxf(v.z, v.w)));
        mn = fminf(mn, fminf(fminf(v.x, v.y), fminf(v.z, v.w)));
    }
    smx[tid] = mx; smn[tid] = mn;
    __syncthreads();
    for (int s = 128; s > 0; s >>= 1) {
        if (tid < s) { smx[tid] = fmaxf(smx[tid], smx[tid + s]); smn[tid] = fminf(smn[tid], smn[tid + s]); }
        __syncthreads();
    }
    if (tid == 0) {
        g_pmax[blockIdx.x] = smx[0];
        g_pmin[blockIdx.x] = smn[0];
        __threadfence();
        atomicAdd(&g_cnt, 1u);
        while (atomicAdd(&g_cnt, 0u) < PREP_GRID) __nanosleep(64);
    }
    __syncthreads();

    // every prep CTA computes the identical scale from the 128 partials
    if (tid < PREP_GRID) { smx[tid] = g_pmax[tid]; smn[tid] = g_pmin[tid]; }
    __syncthreads();
    for (int s = 64; s > 0; s >>= 1) {
        if (tid < s) { smx[tid] = fmaxf(smx[tid], smx[tid + s]); smn[tid] = fminf(smn[tid], smn[tid + s]); }
        __syncthreads();
    }
    const float scl = fmaxf(__fdiv_rn(smx[0] - smn[0], 254.0f), 1e-8f);   // (max-min)/(2*qmax)
    if (blockIdx.x == 0 && tid == 0) g_scale = scl;

    // phase 2: quantize this CTA's chunk (x is L2-hot from phase 1)
#pragma unroll
    for (int i = 0; i < 16; i++) {
        const int e = base + i * 256;
        float4 v = x4[e];
        float q0 = fminf(fmaxf(rintf(__fdiv_rn(v.x, scl)), -127.f), 127.f);
        float q1 = fminf(fmaxf(rintf(__fdiv_rn(v.y, scl)), -127.f), 127.f);
        float q2 = fminf(fmaxf(rintf(__fdiv_rn(v.z, scl)), -127.f), 127.f);
        float q3 = fminf(fmaxf(rintf(__fdiv_rn(v.w, scl)), -127.f), 127.f);
        union { __half h[4]; uint2 u; } pk;
        pk.h[0] = __float2half_rn(q0);
        pk.h[1] = __float2half_rn(q1);
        pk.h[2] = __float2half_rn(q2);
        pk.h[3] = __float2half_rn(q3);
        ((uint2*)g_q)[e] = pk.u;
    }
    __syncthreads();
    if (tid == 0) {
        unsigned o = atomicAdd(&g_cnt2, 1u);
        if (o == PREP_GRID - 1) { g_cnt = 0; g_cnt2 = 0; }   // reset for next replay
    }
}

// ---------------- buildw path: W tile per (j,k) with tensor cores ----------------
__device__ __forceinline__ void buildw_body(int bid, char* sm,
                                            const float* __restrict__ Ysign,
                                            const float* __restrict__ Zsign,
                                            const float* __restrict__ Yscale,
                                            const float* __restrict__ Zscale,
                                            const float* __restrict__ Aq) {
    __nv_bfloat16* sY0 = (__nv_bfloat16*)(sm + SY_OFF);
    __nv_bfloat16* sY1 = (__nv_bfloat16*)(sm + SY_OFF + MM * YPITCH * 2);
    __nv_bfloat16* sZ0 = (__nv_bfloat16*)(sm + SZ_OFF);
    __nv_bfloat16* sZ1 = (__nv_bfloat16*)(sm + SZ_OFF + LL * ZPITCH * 2);
    float* sB  = (float*)(sm + SB_OFF);
    float* sZr = (float*)(sm + SZR_OFF);
    uint32_t* sO = (uint32_t*)(sm + SO_OFF);   // overlays sY; valid after af ldsm + barrier

    const int j = bid >> 5;
    const int k = bid & 31;
    const int tid = threadIdx.x;
    const int lane = tid & 31;
    const int wid = tid >> 5;

    float ysc[2], zsc[2], a0c[2], a1c[2], a2c[2];
    float a3s = 0.f;
#pragma unroll
    for (int p = 0; p < 2; p++) {
        int idx = (p * JJ + j) * KK + k;
        ysc[p] = Yscale[idx]; zsc[p] = Zscale[idx];
        a0c[p] = Aq[idx * 4 + 0]; a1c[p] = Aq[idx * 4 + 1];
        a2c[p] = Aq[idx * 4 + 2]; a3s += Aq[idx * 4 + 3];
        size_t base = (size_t)idx * (MM * LL);   // 2048 floats (== LL*NN)
        const float4* ys4 = (const float4*)(Ysign + base);
        const float4* zs4 = (const float4*)(Zsign + base);
        __nv_bfloat16* sYp = p ? sY1 : sY0;
        __nv_bfloat16* sZp = p ? sZ1 : sZ0;
#pragma unroll
        for (int i = 0; i < 2; i++) {
            int e4 = tid + i * 256;            // 0..511
            int e = e4 * 4;
            // Y: (m,l) with l fastest, 16 per row
            float4 v = ys4[e4];
            int m = e >> 4, l = e & 15;
            __nv_bfloat162* dy = (__nv_bfloat162*)(&sYp[m * YPITCH + l]);
            dy[0] = __nv_bfloat162{__float2bfloat16(v.x), __float2bfloat16(v.y)};
            dy[1] = __nv_bfloat162{__float2bfloat16(v.z), __float2bfloat16(v.w)};
            // Z: (l,n) with n fastest, 128 per row
            float4 w4 = zs4[e4];
            int zl = e >> 7, n = e & 127;
            __nv_bfloat162* dz = (__nv_bfloat162*)(&sZp[zl * ZPITCH + n]);
            dz[0] = __nv_bfloat162{__float2bfloat16(w4.x), __float2bfloat16(w4.y)};
            dz[1] = __nv_bfloat162{__float2bfloat16(w4.z), __float2bfloat16(w4.w)};
        }
    }
    __syncthreads();

    // row/col sign sums -> coefficient vectors
    if (tid < 128) {
        int m = tid; float s0 = 0.f, s1 = 0.f;
#pragma unroll
        for (int l = 0; l < 16; l++) {
            s0 += __bfloat162float(sY0[m * YPITCH + l]);
            s1 += __bfloat162float(sY1[m * YPITCH + l]);
        }
        sB[m] = a1c[0] * ysc[0] * s0 + a1c[1] * ysc[1] * s1;
    } else {
        int n = tid - 128; float s0 = 0.f, s1 = 0.f;
#pragma unroll
        for (int l = 0; l < 16; l++) {
            s0 += __bfloat162float(sZ0[l * ZPITCH + n]);
            s1 += __bfloat162float(sZ1[l * ZPITCH + n]);
        }
        sZr[n] = a2c[0] * zsc[0] * s0 + a2c[1] * zsc[1] * s1;
    }
    __syncthreads();

    const float c00 = a0c[0] * ysc[0] * zsc[0];
    const float c01 = a0c[1] * ysc[1] * zsc[1];
    const int mb = wid * 16;   // warp's m strip

    // A fragments (16x16, row-major m x l), one per p, loaded once.
    // sY is dead after these ldsm; the barrier below makes the sO overlay safe.
    uint32_t aoff = (uint32_t)((mb + (lane & 15)) * (YPITCH * 2)) + (uint32_t)((lane >> 4) * 16);
    uint32_t af0[4], af1[4];
    ldsm4(af0, smem_u32(sY0) + aoff);
    ldsm4(af1, smem_u32(sY1) + aoff);
    __syncthreads();   // all af ldsm complete before any warp writes sO (overlays sY)

    // B trans-ldsm lane addressing: source rows = l (k dim), cols = n
    uint32_t zoff = (uint32_t)((lane & 15) * (ZPITCH * 2)) + (uint32_t)(((lane >> 4) * 8) * 2);
    const uint32_t zb0 = smem_u32(sZ0) + zoff;
    const uint32_t zb1 = smem_u32(sZ1) + zoff;

    const int r0 = mb + (lane >> 2);
    const int r1 = r0 + 8;
    const float sb0 = sB[r0];
    const float sb1 = sB[r1];
    const int so0 = r0 * (OPITCH / 2);   // uint32 row base
    const int so1 = r1 * (OPITCH / 2);

#pragma unroll
    for (int nc = 0; nc < 4; nc++) {
        const int n0 = nc * 32;
        uint32_t b0a[4], b0b[4], b1a[4], b1b[4];
        ldsm4t(b0a, zb0 + (uint32_t)(n0 * 2));          // p0, n-tiles 0,1
        ldsm4t(b0b, zb0 + (uint32_t)((n0 + 16) * 2));   // p0, n-tiles 2,3
        ldsm4t(b1a, zb1 + (uint32_t)(n0 * 2));
        ldsm4t(b1b, zb1 + (uint32_t)((n0 + 16) * 2));

        float acc0[4][4], acc1[4][4];
#pragma unroll
        for (int t = 0; t < 4; t++)
#pragma unroll
            for (int v = 0; v < 4; v++) { acc0[t][v] = 0.f; acc1[t][v] = 0.f; }

        mma16816_bf(acc0[0], af0, &b0a[0]); mma16816_bf(acc0[1], af0, &b0a[2]);
        mma16816_bf(acc0[2], af0, &b0b[0]); mma16816_bf(acc0[3], af0, &b0b[2]);
        mma16816_bf(acc1[0], af1, &b1a[0]); mma16816_bf(acc1[1], af1, &b1a[2]);
        mma16816_bf(acc1[2], af1, &b1b[0]); mma16816_bf(acc1[3], af1, &b1b[2]);

#pragma unroll
        for (int nt = 0; nt < 4; nt++) {
            const int col = n0 + nt * 8 + (lane & 3) * 2;
            const float2 zr = *(const float2*)(&sZr[col]);
            const float add0 = zr.x + a3s;
            const float add1 = zr.y + a3s;
            float w00 = c00 * acc0[nt][0] + c01 * acc1[nt][0] + sb0 + add0;
            float w01 = c00 * acc0[nt][1] + c01 * acc1[nt][1] + sb0 + add1;
            float w10 = c00 * acc0[nt][2] + c01 * acc1[nt][2] + sb1 + add0;
            float w11 = c00 * acc0[nt][3] + c01 * acc1[nt][3] + sb1 + add1;

            union { __half h[2]; uint32_t u; } pk;
            pk.h[0] = __float2half_rn(w00); pk.h[1] = __float2half_rn(w01);
            sO[so0 + (col >> 1)] = pk.u;
            pk.h[0] = __float2half_rn(w10); pk.h[1] = __float2half_rn(w11);
            sO[so1 + (col >> 1)] = pk.u;
        }
    }
    __syncthreads();

    // coalesced store: 128 rows x 256 B, full 128B lines
    const char* sob = sm + SO_OFF;
    char* gw = (char*)(g_W + (size_t)(j * 128) * KN + k * 128);
#pragma unroll
    for (int it = 0; it < 8; it++) {
        int c = tid + it * 256;         // 0..2047
        int row = c >> 4;
        int seg = c & 15;
        uint4 v = *(const uint4*)(sob + row * (OPITCH * 2) + seg * 16);
        *(uint4*)(gw + (size_t)row * (KN * 2) + seg * 16) = v;
    }
}

// ---------------- fused kernel: prep (CTAs 0..127) + buildw (CTAs 128..1151) ----------------
// __launch_bounds__(256, 4): cap regs at 64 so smem (43.5 KB) and regs both
// allow 4 CTAs/SM -> 1.95 waves for the 1152-CTA grid instead of 2.6.
__global__ void __launch_bounds__(256, 4) k_pb(const float* __restrict__ x,
                                               const float* __restrict__ Ysign,
                                               const float* __restrict__ Zsign,
                                               const float* __restrict__ Yscale,
                                               const float* __restrict__ Zscale,
                                               const float* __restrict__ Aq) {
    extern __shared__ char sm[];
    if (blockIdx.x < PREP_GRID) {
        prep_body(x, sm);
    } else {
        buildw_body(blockIdx.x - PREP_GRID, sm, Ysign, Zsign, Yscale, Zscale, Aq);
    }
}

// ---------------- kernel: warp-MMA GEMM out = act*(q @ W^T) + bias ----------------
// R13 configuration (the measured mma.sync fp32-accum plateau, 54.4us):
// CTA tile 64(b) x 128(jm), 128 threads = 4 warps (2m x 2n), warp tile 32x64,
// K-chunk 64, 4-stage cp.async pipeline, 2 CTAs/SM, register-double-buffered
// fragments (ldsm(ks+1) before mma(ks)).
__global__ void __launch_bounds__(128, 2) k_gemm(const float* __restrict__ bias,
                                                 float* __restrict__ out) {
    extern __shared__ char smem[];
    const uint32_t sbase = smem_u32(smem);

    const int tid = threadIdx.x;
    const int lane = tid & 31;
    const int wid = tid >> 5;
    const int jt = blockIdx.x;        // jm tile, 0..31
    const int bt = blockIdx.y;        // b tile,  0..7 (64 rows each)
    const int warp_m = wid & 1;       // 0..1 -> m base warp_m*32
    const int warp_n = wid >> 1;      // 0..1 -> n base warp_n*64

    // ---- cp.async source/dest offsets ----
    uint32_t swoffA[4]; const char* srcq[4];
    uint32_t swoffW[8]; const char* srcw[8];
    {
        const char* gq = (const char*)(g_q + (size_t)(bt * 64) * KN);
        const char* gw = (const char*)(g_W + (size_t)(jt * 128) * KN);
#pragma unroll
        for (int i = 0; i < 4; i++) {
            int idx = tid + i * 128;            // 0..511
            int row = idx >> 3;                 // 0..63
            int seg = (idx & 7) * 16;
            swoffA[i] = (uint32_t)(row * 128) + ((uint32_t)seg ^ (uint32_t)((row & 7) << 4));
            srcq[i] = gq + (size_t)row * (KN * 2) + seg;
        }
#pragma unroll
        for (int i = 0; i < 8; i++) {
            int idx = tid + i * 128;            // 0..1023
            int row = idx >> 3;                 // 0..127
            int seg = (idx & 7) * 16;
            swoffW[i] = (uint32_t)(row * 128) + ((uint32_t)seg ^ (uint32_t)((row & 7) << 4));
            srcw[i] = gw + (size_t)row * (KN * 2) + seg;
        }
    }

    // ---- prefetch chunks 0..2 ----
#pragma unroll
    for (int s = 0; s < NSTG - 1; s++) {
        uint32_t base = sbase + s * STAGE;
        size_t koff = (size_t)s * 128;          // 64 fp16 = 128 bytes
#pragma unroll
        for (int i = 0; i < 4; i++) cp16(base + swoffA[i], srcq[i] + koff);
#pragma unroll
        for (int i = 0; i < 8; i++) cp16(base + 8192 + swoffW[i], srcw[i] + koff);
        CP_COMMIT();
    }

    // ---- ldmatrix lane addressing ----
    const int a_row = warp_m * 32 + (lane & 15);           // + mt*16
    const uint32_t a_hi  = (uint32_t)((lane >> 4) * 16);
    const uint32_t a_swz = (uint32_t)((a_row & 7) << 4);   // invariant under +16
    const int b_g = lane >> 3;                              // 0..3
    const int b_row0 = warp_n * 64 + ((b_g >> 1) << 3) + (lane & 7);  // + i*16
    const uint32_t b_hi  = (uint32_t)((b_g & 1) * 16);
    const uint32_t b_swz = (uint32_t)((b_row0 & 7) << 4);  // invariant under +16

    float acc[2][8][4];
#pragma unroll
    for (int mt = 0; mt < 2; mt++)
#pragma unroll
        for (int nt = 0; nt < 8; nt++)
#pragma unroll
            for (int v = 0; v < 4; v++) acc[mt][nt][v] = 0.f;

    // register-double-buffered fragments
    uint32_t a_fr[2][2][4];   // [buf][mt][4]
    uint32_t b_fr[2][8][2];   // [buf][nt][2]

    for (int c = 0; c < NCHUNK; c++) {
        CP_WAIT(1);              // chunk c landed (only c+1's group may remain)
        __syncthreads();         // all threads see chunk c AND finished compute(c-1)

        // issue chunk c+3 into buffer (c+3)%4 == (c-1)%4, freed by the barrier above
        if (c + 3 < NCHUNK) {
            uint32_t base = sbase + ((c + 3) % NSTG) * STAGE;
            size_t koff = (size_t)(c + 3) * 128;
#pragma unroll
            for (int i = 0; i < 4; i++) cp16(base + swoffA[i], srcq[i] + koff);
#pragma unroll
            for (int i = 0; i < 8; i++) cp16(base + 8192 + swoffW[i], srcw[i] + koff);
        }
        CP_COMMIT();             // fixed group accounting (empty at tail)

        const uint32_t bb = sbase + (c % NSTG) * STAGE;

        // load ks=0 fragments into buf 0
#pragma unroll
        for (int mt = 0; mt < 2; mt++)
            ldsm4(a_fr[0][mt], bb + (uint32_t)((a_row + mt * 16) * 128) + (a_hi ^ a_swz));
#pragma unroll
        for (int i = 0; i < 4; i++) {
            uint32_t ro = (uint32_t)((b_row0 + i * 16) * 128) + (b_hi ^ b_swz);
            uint32_t r[4];
            ldsm4(r, bb + 8192 + ro);
            b_fr[0][2*i][0] = r[0]; b_fr[0][2*i][1] = r[1];
            b_fr[0][2*i+1][0] = r[2]; b_fr[0][2*i+1][1] = r[3];
        }

#pragma unroll
        for (int ks = 0; ks < 4; ks++) {
            const int cur = ks & 1;
            const int nxt = cur ^ 1;
            if (ks < 3) {
                const uint32_t kso = (uint32_t)((ks + 1) * 32);
#pragma unroll
                for (int mt = 0; mt < 2; mt++)
                    ldsm4(a_fr[nxt][mt], bb + (uint32_t)((a_row + mt * 16) * 128)
                                          + ((kso + a_hi) ^ a_swz));
#pragma unroll
                for (int i = 0; i < 4; i++) {
                    uint32_t ro = (uint32_t)((b_row0 + i * 16) * 128)
                                + ((kso + b_hi) ^ b_swz);
                    uint32_t r[4];
                    ldsm4(r, bb + 8192 + ro);
                    b_fr[nxt][2*i][0] = r[0]; b_fr[nxt][2*i][1] = r[1];
                    b_fr[nxt][2*i+1][0] = r[2]; b_fr[nxt][2*i+1][1] = r[3];
                }
            }
#pragma unroll
            for (int mt = 0; mt < 2; mt++)
#pragma unroll
                for (int nt = 0; nt < 8; nt++)
                    mma16816_f16(acc[mt][nt], a_fr[cur][mt], b_fr[cur][nt]);
        }
    }

    // ---- epilogue: out = acc*act + bias ----
    const float act = g_scale;
    const int orow0 = bt * 64 + warp_m * 32 + (lane >> 2);
    const int ocol0 = jt * 128 + warp_n * 64 + (lane & 3) * 2;
#pragma unroll
    for (int mt = 0; mt < 2; mt++) {
        const int r0 = orow0 + mt * 16;
#pragma unroll
        for (int nt = 0; nt < 8; nt++) {
            const int col = ocol0 + nt * 8;
            const float2 b2 = *(const float2*)(bias + col);
            float2 v0, v1;
            v0.x = acc[mt][nt][0] * act + b2.x;
            v0.y = acc[mt][nt][1] * act + b2.y;
            v1.x = acc[mt][nt][2] * act + b2.x;
            v1.y = acc[mt][nt][3] * act + b2.y;
            *(float2*)(out + (size_t)r0 * JM + col)       = v0;
            *(float2*)(out + (size_t)(r0 + 8) * JM + col) = v1;
        }
    }
}

// ---------------- launcher ----------------
extern "C" void kernel_launch(void* const* d_in, const int* in_sizes, int n_in,
                              void* d_out, int out_size) {
    const float *x = nullptr, *Ys = nullptr, *Zs = nullptr;
    const float *Ysc = nullptr, *Zsc = nullptr, *A = nullptr, *bias = nullptr;
    for (int i = 0; i < n_in; i++) {
        const int s = in_sizes[i];
        const float* p = (const float*)d_in[i];
        if (s == BATCH * KN && !x) x = p;                                        // 2097152
        else if (s == PP * JJ * KK * MM * LL) { if (!Ys) Ys = p; else Zs = p; }  // 4194304 x2
        else if (s == PP * JJ * KK) { if (!Ysc) Ysc = p; else Zsc = p; }         // 2048 x2
        else if (s == PP * JJ * KK * 4) A = p;                                   // 8192
        else if (s == JM) bias = p;                                              // 4096
    }
    float* out = (float*)d_out;

    cudaFuncSetAttribute(k_pb, cudaFuncAttributeMaxDynamicSharedMemorySize, BW_SMEM);
    k_pb<<<PREP_GRID + JJ * KK, 256, BW_SMEM>>>(x, Ys, Zs, Ysc, Zsc, A);

    const int smem_bytes = NSTG * STAGE;   // 98304
    cudaFuncSetAttribute(k_gemm, cudaFuncAttributeMaxDynamicSharedMemorySize, smem_bytes);
    dim3 grid(JM / 128, BATCH / 64);
    k_gemm<<<grid, 128, smem_bytes>>>(bias, out);
}